// round 15
// baseline (speedup 1.0000x reference)
#include <cuda_runtime.h>
#include <cuda_fp16.h>
#include <stdint.h>

// ----------------------------------------------------------------------------
// SpectralPooling via HMMA (mma.sync m16n8k16 fp16, single product) GEMMs.
// y = idctn(pad(crop(dctn(x)))); axes 0,1 cancel. Per-axis operator
// B[o][i] = sum_{k<28} D32[k,o]*D64[k,i]  (32x64), applied along axes 2,3,4.
// Three stages, each GEMM [rows x 64] -> [rows x 32] against B^T; outputs are
// written "pre-transposed" so K is always contiguous and stores coalesce:
//   stage1 (SB=12): X[b][i0][i1][i2]   -> T1[b][o2][i0][i1]   (fp16)
//   stage2 (SB=11): T1[b][o2][i0][i1]  -> T2[b][o1][o2][i0]   (fp16)
//   stage3 (SB=10): T2[b][o1][o2][i0]  -> Y[b][o0][o1][o2]    (fp32)
// out_addr(m,c) = (m>>SB)*(32<<SB) + c*(1<<SB) + (m & ((1<<SB)-1))  [elements]
// Precision: A and B plain fp16, fp32 accumulate (measured rel ~5.4e-4).
// Stage-2/3 A tiles copied with cp.async; those stages run 6 CTAs/SM
// (regs<=85), stage 1 keeps 5 (its loader holds 16 float4 in flight).
// ----------------------------------------------------------------------------

__device__ __half g_Bh[2048];      // B fp16, row-major [o][i] (32x64)
__device__ __half g_T1[33554432];  // 64 MB
__device__ __half g_T2[16777216];  // 32 MB

__device__ __forceinline__ uint32_t smem_u32(const void* p) {
    uint32_t a;
    asm("{ .reg .u64 t; cvta.to.shared.u64 t, %1; cvt.u32.u64 %0, t; }"
        : "=r"(a) : "l"(p));
    return a;
}

// ---------------- init: one warp per B element, lane = k-term -------------------
__global__ void init_B_kernel() {
    int gw   = (blockIdx.x * blockDim.x + threadIdx.x) >> 5;  // 0..2047
    int lane = threadIdx.x & 31;
    if (gw >= 2048) return;
    int o = gw >> 6;   // 0..31
    int i = gw & 63;   // 0..63
    float term = 0.0f;
    if (lane < 28) {
        const float s32_0 = 0.17677669529663688f;  // sqrt(1/32)
        const float s32_k = 0.25f;                 // sqrt(2/32)
        const float s64_0 = 0.125f;                // sqrt(1/64)
        const float s64_k = 0.17677669529663688f;  // sqrt(2/64)
        float a32 = (2.0f * o + 1.0f) * (float)lane / 64.0f;
        float a64 = (2.0f * i + 1.0f) * (float)lane / 128.0f;
        float d32 = ((lane == 0) ? s32_0 : s32_k) * cospif(a32);
        float d64 = ((lane == 0) ? s64_0 : s64_k) * cospif(a64);
        term = d32 * d64;
    }
    #pragma unroll
    for (int s = 16; s > 0; s >>= 1)
        term += __shfl_xor_sync(0xFFFFFFFFu, term, s);
    if (lane == 0)
        g_Bh[gw] = __float2half_rn(term);
}

// ---------------- mma.sync / ldmatrix / cp.async wrappers --------------------------
__device__ __forceinline__ void mma16816(float* d, const uint32_t* a,
                                         const uint32_t* b) {
    asm("mma.sync.aligned.m16n8k16.row.col.f32.f16.f16.f32 "
        "{%0,%1,%2,%3}, {%4,%5,%6,%7}, {%8,%9}, {%0,%1,%2,%3};"
        : "+f"(d[0]), "+f"(d[1]), "+f"(d[2]), "+f"(d[3])
        : "r"(a[0]), "r"(a[1]), "r"(a[2]), "r"(a[3]), "r"(b[0]), "r"(b[1]));
}

__device__ __forceinline__ void ldsm4(uint32_t* r, uint32_t addr) {
    asm volatile("ldmatrix.sync.aligned.m8n8.x4.shared.b16 {%0,%1,%2,%3}, [%4];"
                 : "=r"(r[0]), "=r"(r[1]), "=r"(r[2]), "=r"(r[3]) : "r"(addr));
}

__device__ __forceinline__ uint32_t cvt_f16x2(float hi, float lo) {
    uint32_t p;
    asm("cvt.rn.f16x2.f32 %0, %1, %2;" : "=r"(p) : "f"(hi), "f"(lo));
    return p;
}

__device__ __forceinline__ void cp16(uint32_t dst, const void* src) {
    asm volatile("cp.async.cg.shared.global [%0], [%1], 16;"
                 :: "r"(dst), "l"(src) : "memory");
}

// ---------------- stage kernel body ------------------------------------------------
// A tile: 128 rows x 64 K fp16 in smem, padded row stride 72 fp16 (144 B).
// Warp w computes rows w*32..w*32+31, all 32 output cols.
// smem: sA 18 KB + sBh 4.5 KB = 22.5 KB.
template<int SB>
__device__ __forceinline__ void stage_body(const float* __restrict__ xin,
                                           float* __restrict__ xout) {
    constexpr bool FIN  = (SB == 12);   // fp32 input (convert in loader)
    constexpr bool FOUT = (SB == 10);   // fp32 output
    constexpr size_t OC = (size_t)1 << SB;   // elements per output column line

    const __half* in16 = (SB == 11) ? g_T1 : g_T2;
    __half* out16      = (SB == 12) ? g_T1 : g_T2;

    __shared__ __align__(16) __half sA[128 * 72];   // 18 KB
    __shared__ __align__(16) __half sBh[32 * 72];   // 4.5 KB

    const int tid = threadIdx.x;
    const int w   = tid >> 5;
    const int lid = tid & 31;
    const int gid = lid >> 2;   // 0..7
    const int tg  = lid & 3;    // 0..3

    const uint32_t uA  = smem_u32(sA);
    const uint32_t uBh = smem_u32(sBh);

    // ---- load A tile (kick off first: longest latency)
    if (FIN) {
        // fp32 input: 2048 float4, convert to fp16 pairs
        const float4* __restrict__ inp =
            (const float4*)(xin + (size_t)blockIdx.x * 8192);
        #pragma unroll
        for (int j = 0; j < 16; ++j) {
            int f = j * 128 + tid;           // float4 index 0..2047
            float4 v = inp[f];
            int r = f >> 4, k4 = f & 15;
            uint32_t p01 = cvt_f16x2(v.y, v.x);
            uint32_t p23 = cvt_f16x2(v.w, v.z);
            *(uint2*)((char*)sA + r * 144 + k4 * 8) = make_uint2(p01, p23);
        }
    } else {
        // fp16 input: 1024 x 16B chunks, cp.async straight into padded smem
        const char* src = (const char*)(in16 + (size_t)blockIdx.x * 8192);
        #pragma unroll
        for (int j = 0; j < 8; ++j) {
            int f = j * 128 + tid;           // chunk index 0..1023
            uint32_t d = uA + (uint32_t)(f >> 3) * 144u + (uint32_t)(f & 7) * 16u;
            cp16(d, src + (size_t)f * 16);
        }
        asm volatile("cp.async.commit_group;" ::: "memory");
    }

    // ---- load B into padded smem (row stride 144 B)
    {
        const uint32_t* bh = (const uint32_t*)g_Bh;
        #pragma unroll
        for (int idx = tid; idx < 1024; idx += 128) {
            int r = idx >> 5, c2 = idx & 31;
            *(uint32_t*)((char*)sBh + r * 144 + c2 * 4) = bh[idx];
        }
    }

    if (!FIN)
        asm volatile("cp.async.wait_group 0;" ::: "memory");
    __syncthreads();

    // ---- per-lane ldmatrix addressing (padded rows, static offsets)
    const int lr = lid & 7, mi = lid >> 3;
    const uint32_t aoff0 =
        (uint32_t)(w * 32 + ((mi & 1) << 3) + lr) * 144u + ((mi >> 1) << 4);
    const uint32_t boff0 =
        (uint32_t)(((mi >> 1) << 3) + lr) * 144u + ((mi & 1) << 4);

    // ---- HMMA mainloop: acc[rt][nt][4], single product A*B
    float acc[2][4][4];
    #pragma unroll
    for (int rt = 0; rt < 2; ++rt)
        #pragma unroll
        for (int nt = 0; nt < 4; ++nt)
            #pragma unroll
            for (int q = 0; q < 4; ++q) acc[rt][nt][q] = 0.0f;

    #pragma unroll
    for (int kk = 0; kk < 4; ++kk) {
        uint32_t ah[2][4];
        #pragma unroll
        for (int rt = 0; rt < 2; ++rt) {
            uint32_t ao = aoff0 + (uint32_t)(rt * 16 * 144) + (uint32_t)(kk * 32);
            ldsm4(ah[rt], uA + ao);
        }
        uint32_t bh[4][2];
        #pragma unroll
        for (int t = 0; t < 2; ++t) {
            uint32_t bo = boff0 + (uint32_t)(t * 16 * 144) + (uint32_t)(kk * 32);
            uint32_t rh[4];
            ldsm4(rh, uBh + bo);
            bh[2 * t][0] = rh[0]; bh[2 * t][1] = rh[1];
            bh[2 * t + 1][0] = rh[2]; bh[2 * t + 1][1] = rh[3];
        }
        #pragma unroll
        for (int rt = 0; rt < 2; ++rt)
            #pragma unroll
            for (int nt = 0; nt < 4; ++nt)
                mma16816(acc[rt][nt], ah[rt], bh[nt]);
    }

    // ---- epilogue: transpose through this warp's own (dead) A region
    __syncwarp();
    float* epw = (float*)((char*)sA + (size_t)w * 32 * 144);   // 32x33 fp32 fits
    #pragma unroll
    for (int rt = 0; rt < 2; ++rt)
        #pragma unroll
        for (int nt = 0; nt < 4; ++nt) {
            int r0 = rt * 16 + gid;
            int c0 = nt * 8 + tg * 2;
            epw[r0 * 33 + c0]           = acc[rt][nt][0];
            epw[r0 * 33 + c0 + 1]       = acc[rt][nt][1];
            epw[(r0 + 8) * 33 + c0]     = acc[rt][nt][2];
            epw[(r0 + 8) * 33 + c0 + 1] = acc[rt][nt][3];
        }
    __syncwarp();

    // ---- coalesced transposed store
    const size_t M0 = (size_t)blockIdx.x * 128;
    const size_t obase = (M0 >> SB) * (OC * 32) + (M0 & (OC - 1));

    if (FOUT) {
        // fp32 output, one column element per iteration
        float* __restrict__ ob = xout + obase + (size_t)(w * 32 + lid);
        const float* eprow = epw + lid * 33;
        #pragma unroll
        for (int c = 0; c < 32; ++c)
            ob[(size_t)c << SB] = eprow[c];
    } else {
        // fp16 output: pack adjacent m-pair into one 4B store
        uint32_t* __restrict__ o32 = (uint32_t*)out16;
        const int cg = lid >> 4;     // 0..1
        const int mp = lid & 15;     // 0..15 -> rows 2mp, 2mp+1
        #pragma unroll
        for (int j = 0; j < 16; ++j) {
            int c = 2 * j + cg;
            float v0 = epw[(2 * mp) * 33 + c];
            float v1 = epw[(2 * mp + 1) * 33 + c];
            uint32_t p = cvt_f16x2(v1, v0);   // low half = even m
            size_t elem = obase + (size_t)c * OC + (size_t)(w * 32 + 2 * mp);
            o32[elem >> 1] = p;
        }
    }
}

// stage 1: loader holds 16 float4 in flight -> keep 5 CTAs/SM reg budget
__global__ __launch_bounds__(128, 5) void stage1_kernel(
        const float* __restrict__ xin, float* __restrict__ xout) {
    stage_body<12>(xin, xout);
}
// stages 2/3: lean cp.async loaders -> 6 CTAs/SM (regs <= 85)
__global__ __launch_bounds__(128, 6) void stage2_kernel(
        const float* __restrict__ xin, float* __restrict__ xout) {
    stage_body<11>(xin, xout);
}
__global__ __launch_bounds__(128, 6) void stage3_kernel(
        const float* __restrict__ xin, float* __restrict__ xout) {
    stage_body<10>(xin, xout);
}

// ---------------- launch ---------------------------------------------------------
extern "C" void kernel_launch(void* const* d_in, const int* in_sizes, int n_in,
                              void* d_out, int out_size) {
    const float* x = (const float*)d_in[0];
    float* out = (float*)d_out;

    init_B_kernel<<<512, 128>>>();

    stage1_kernel<<<8192, 128>>>(x, out);   // X  -> T1   (contract i2)
    stage2_kernel<<<4096, 128>>>(x, out);   // T1 -> T2   (contract i1)
    stage3_kernel<<<2048, 128>>>(x, out);   // T2 -> out  (contract i0)
}

// round 17
// speedup vs baseline: 1.1468x; 1.1468x over previous
#include <cuda_runtime.h>
#include <cuda_fp16.h>
#include <stdint.h>

// ----------------------------------------------------------------------------
// SpectralPooling via HMMA (mma.sync m16n8k16 fp16, single product) GEMMs.
// y = idctn(pad(crop(dctn(x)))); axes 0,1 cancel. Per-axis operator
// B[o][i] = sum_{k<28} D32[k,o]*D64[k,i]  (32x64), applied along axes 2,3,4.
// Three stages, each GEMM [rows x 64] -> [rows x 32] against B^T; outputs are
// written "pre-transposed" so K is always contiguous and stores coalesce:
//   stage1 (SB=12): X[b][i0][i1][i2]   -> T1[b][o2][i0][i1]   (fp16)
//   stage2 (SB=11): T1[b][o2][i0][i1]  -> T2[b][o1][o2][i0]   (fp16)
//   stage3 (SB=10): T2[b][o1][o2][i0]  -> Y[b][o0][o1][o2]    (fp32)
// out_addr(m,c) = (m>>SB)*(32<<SB) + c*(1<<SB) + (m & ((1<<SB)-1))  [elements]
// Precision: A and B plain fp16, fp32 accumulate (measured rel ~5.4e-4).
// L2 policy (cache_hint + createpolicy evict_first): stage1 input and T1/T2
// reads are single-use streams -> keep T1/T2 L2-resident for consumer stage.
// Epilogue stores vectorized (STG.128 fp32 / STG.64 fp16).
// ----------------------------------------------------------------------------

__device__ __half g_Bh[2048];      // B fp16, row-major [o][i] (32x64)
__device__ __half g_T1[33554432];  // 64 MB
__device__ __half g_T2[16777216];  // 32 MB

__device__ __forceinline__ uint32_t smem_u32(const void* p) {
    uint32_t a;
    asm("{ .reg .u64 t; cvta.to.shared.u64 t, %1; cvt.u32.u64 %0, t; }"
        : "=r"(a) : "l"(p));
    return a;
}

// ---------------- init: one warp per B element, lane = k-term -------------------
__global__ void init_B_kernel() {
    int gw   = (blockIdx.x * blockDim.x + threadIdx.x) >> 5;  // 0..2047
    int lane = threadIdx.x & 31;
    if (gw >= 2048) return;
    int o = gw >> 6;   // 0..31
    int i = gw & 63;   // 0..63
    float term = 0.0f;
    if (lane < 28) {
        const float s32_0 = 0.17677669529663688f;  // sqrt(1/32)
        const float s32_k = 0.25f;                 // sqrt(2/32)
        const float s64_0 = 0.125f;                // sqrt(1/64)
        const float s64_k = 0.17677669529663688f;  // sqrt(2/64)
        float a32 = (2.0f * o + 1.0f) * (float)lane / 64.0f;
        float a64 = (2.0f * i + 1.0f) * (float)lane / 128.0f;
        float d32 = ((lane == 0) ? s32_0 : s32_k) * cospif(a32);
        float d64 = ((lane == 0) ? s64_0 : s64_k) * cospif(a64);
        term = d32 * d64;
    }
    #pragma unroll
    for (int s = 16; s > 0; s >>= 1)
        term += __shfl_xor_sync(0xFFFFFFFFu, term, s);
    if (lane == 0)
        g_Bh[gw] = __float2half_rn(term);
}

// ---------------- wrappers ----------------------------------------------------------
__device__ __forceinline__ void mma16816(float* d, const uint32_t* a,
                                         const uint32_t* b) {
    asm("mma.sync.aligned.m16n8k16.row.col.f32.f16.f16.f32 "
        "{%0,%1,%2,%3}, {%4,%5,%6,%7}, {%8,%9}, {%0,%1,%2,%3};"
        : "+f"(d[0]), "+f"(d[1]), "+f"(d[2]), "+f"(d[3])
        : "r"(a[0]), "r"(a[1]), "r"(a[2]), "r"(a[3]), "r"(b[0]), "r"(b[1]));
}

__device__ __forceinline__ void ldsm4(uint32_t* r, uint32_t addr) {
    asm volatile("ldmatrix.sync.aligned.m8n8.x4.shared.b16 {%0,%1,%2,%3}, [%4];"
                 : "=r"(r[0]), "=r"(r[1]), "=r"(r[2]), "=r"(r[3]) : "r"(addr));
}

__device__ __forceinline__ uint32_t cvt_f16x2(float hi, float lo) {
    uint32_t p;
    asm("cvt.rn.f16x2.f32 %0, %1, %2;" : "=r"(p) : "f"(hi), "f"(lo));
    return p;
}

__device__ __forceinline__ uint64_t mk_evict_first_policy() {
    uint64_t pol;
    asm("createpolicy.fractional.L2::evict_first.b64 %0, 1.0;" : "=l"(pol));
    return pol;
}

// streaming fp32 load with evict_first policy (cache_hint form: any width ok)
__device__ __forceinline__ float4 ldg_ef(const float4* p, uint64_t pol) {
    float4 v;
    asm("ld.global.nc.L2::cache_hint.v4.f32 {%0,%1,%2,%3}, [%4], %5;"
        : "=f"(v.x), "=f"(v.y), "=f"(v.z), "=f"(v.w) : "l"(p), "l"(pol));
    return v;
}

// cp.async with evict_first cache policy
__device__ __forceinline__ void cp16_ef(uint32_t dst, const void* src,
                                        uint64_t pol) {
    asm volatile("cp.async.cg.shared.global.L2::cache_hint [%0], [%1], 16, %2;"
                 :: "r"(dst), "l"(src), "l"(pol) : "memory");
}

// ---------------- stage kernel --------------------------------------------------
// A tile: 128 rows x 64 K fp16 in smem, padded row stride 72 fp16 (144 B).
// Warp w computes rows w*32..w*32+31, all 32 output cols.
// smem: sA 18 KB + sBh 4.5 KB = 22.5 KB.
template<int SB>
__global__ __launch_bounds__(128, 5) void stage_kernel(
        const float* __restrict__ xin, float* __restrict__ xout) {
    constexpr bool FIN  = (SB == 12);   // fp32 input (convert in loader)
    constexpr bool FOUT = (SB == 10);   // fp32 output
    constexpr size_t OC = (size_t)1 << SB;   // elements per output column line

    const __half* in16 = (SB == 11) ? g_T1 : g_T2;
    __half* out16      = (SB == 12) ? g_T1 : g_T2;

    __shared__ __align__(16) __half sA[128 * 72];   // 18 KB
    __shared__ __align__(16) __half sBh[32 * 72];   // 4.5 KB

    const int tid = threadIdx.x;
    const int w   = tid >> 5;
    const int lid = tid & 31;

    const uint32_t uA  = smem_u32(sA);
    const uint32_t uBh = smem_u32(sBh);

    // ---- load A tile (kick off first: longest latency)
    if (FIN) {
        // fp32 input: 2048 float4, evict_first stream, convert to fp16 pairs
        const uint64_t pol = mk_evict_first_policy();
        const float4* __restrict__ inp =
            (const float4*)(xin + (size_t)blockIdx.x * 8192);
        #pragma unroll
        for (int j = 0; j < 16; ++j) {
            int f = j * 128 + tid;           // float4 index 0..2047
            float4 v = ldg_ef(inp + f, pol);
            int r = f >> 4, k4 = f & 15;
            uint32_t p01 = cvt_f16x2(v.y, v.x);
            uint32_t p23 = cvt_f16x2(v.w, v.z);
            *(uint2*)((char*)sA + r * 144 + k4 * 8) = make_uint2(p01, p23);
        }
    } else {
        // fp16 input (single-use): cp.async with evict_first policy
        const uint64_t pol = mk_evict_first_policy();
        const char* src = (const char*)(in16 + (size_t)blockIdx.x * 8192);
        #pragma unroll
        for (int j = 0; j < 8; ++j) {
            int f = j * 128 + tid;           // chunk index 0..1023
            uint32_t d = uA + (uint32_t)(f >> 3) * 144u + (uint32_t)(f & 7) * 16u;
            cp16_ef(d, src + (size_t)f * 16, pol);
        }
        asm volatile("cp.async.commit_group;" ::: "memory");
    }

    // ---- load B into padded smem (row stride 144 B)
    {
        const uint32_t* bh = (const uint32_t*)g_Bh;
        #pragma unroll
        for (int idx = tid; idx < 1024; idx += 128) {
            int r = idx >> 5, c2 = idx & 31;
            *(uint32_t*)((char*)sBh + r * 144 + c2 * 4) = bh[idx];
        }
    }

    if (!FIN)
        asm volatile("cp.async.wait_group 0;" ::: "memory");
    __syncthreads();

    // ---- per-lane ldmatrix addressing (padded rows, static offsets)
    const int lr = lid & 7, mi = lid >> 3;
    const uint32_t aoff0 =
        (uint32_t)(w * 32 + ((mi & 1) << 3) + lr) * 144u + ((mi >> 1) << 4);
    const uint32_t boff0 =
        (uint32_t)(((mi >> 1) << 3) + lr) * 144u + ((mi & 1) << 4);

    // ---- HMMA mainloop: acc[rt][nt][4], single product A*B
    float acc[2][4][4];
    #pragma unroll
    for (int rt = 0; rt < 2; ++rt)
        #pragma unroll
        for (int nt = 0; nt < 4; ++nt)
            #pragma unroll
            for (int q = 0; q < 4; ++q) acc[rt][nt][q] = 0.0f;

    #pragma unroll
    for (int kk = 0; kk < 4; ++kk) {
        uint32_t ah[2][4];
        #pragma unroll
        for (int rt = 0; rt < 2; ++rt) {
            uint32_t ao = aoff0 + (uint32_t)(rt * 16 * 144) + (uint32_t)(kk * 32);
            ldsm4(ah[rt], uA + ao);
        }
        uint32_t bh[4][2];
        #pragma unroll
        for (int t = 0; t < 2; ++t) {
            uint32_t bo = boff0 + (uint32_t)(t * 16 * 144) + (uint32_t)(kk * 32);
            uint32_t rh[4];
            ldsm4(rh, uBh + bo);
            bh[2 * t][0] = rh[0]; bh[2 * t][1] = rh[1];
            bh[2 * t + 1][0] = rh[2]; bh[2 * t + 1][1] = rh[3];
        }
        #pragma unroll
        for (int rt = 0; rt < 2; ++rt)
            #pragma unroll
            for (int nt = 0; nt < 4; ++nt)
                mma16816(acc[rt][nt], ah[rt], bh[nt]);
    }

    // ---- epilogue: transpose through this warp's own (dead) A region
    const int gid = lid >> 2;   // 0..7
    const int tg  = lid & 3;    // 0..3
    __syncwarp();
    float* epw = (float*)((char*)sA + (size_t)w * 32 * 144);   // 32x33 fp32 fits
    #pragma unroll
    for (int rt = 0; rt < 2; ++rt)
        #pragma unroll
        for (int nt = 0; nt < 4; ++nt) {
            int r0 = rt * 16 + gid;
            int c0 = nt * 8 + tg * 2;
            epw[r0 * 33 + c0]           = acc[rt][nt][0];
            epw[r0 * 33 + c0 + 1]       = acc[rt][nt][1];
            epw[(r0 + 8) * 33 + c0]     = acc[rt][nt][2];
            epw[(r0 + 8) * 33 + c0 + 1] = acc[rt][nt][3];
        }
    __syncwarp();

    // ---- coalesced transposed store, vectorized (4 m per thread-store)
    const size_t M0 = (size_t)blockIdx.x * 128;
    const size_t obase = (M0 >> SB) * (OC * 32) + (M0 & (OC - 1));
    const int mq = (lid & 7) * 4;    // m-group within warp rows
    const int cb = lid >> 3;         // column sub-index 0..3

    if (FOUT) {
        // fp32 output: STG.128 of 4 consecutive m per column
        #pragma unroll
        for (int j = 0; j < 8; ++j) {
            int c = j * 4 + cb;
            float4 v = make_float4(epw[(mq + 0) * 33 + c],
                                   epw[(mq + 1) * 33 + c],
                                   epw[(mq + 2) * 33 + c],
                                   epw[(mq + 3) * 33 + c]);
            size_t elem = obase + (size_t)c * OC + (size_t)(w * 32 + mq);
            *(float4*)(xout + elem) = v;
        }
    } else {
        // fp16 output: STG.64 of 4 consecutive m per column
        #pragma unroll
        for (int j = 0; j < 8; ++j) {
            int c = j * 4 + cb;
            uint32_t p0 = cvt_f16x2(epw[(mq + 1) * 33 + c],
                                    epw[(mq + 0) * 33 + c]);
            uint32_t p1 = cvt_f16x2(epw[(mq + 3) * 33 + c],
                                    epw[(mq + 2) * 33 + c]);
            size_t elem = obase + (size_t)c * OC + (size_t)(w * 32 + mq);
            *(uint2*)(out16 + elem) = make_uint2(p0, p1);
        }
    }
}

// ---------------- launch ---------------------------------------------------------
extern "C" void kernel_launch(void* const* d_in, const int* in_sizes, int n_in,
                              void* d_out, int out_size) {
    const float* x = (const float*)d_in[0];
    float* out = (float*)d_out;

    init_B_kernel<<<512, 128>>>();

    stage_kernel<12><<<8192, 128>>>(x, out);   // X  -> T1   (contract i2)
    stage_kernel<11><<<4096, 128>>>(x, out);   // T1 -> T2   (contract i1)
    stage_kernel<10><<<2048, 128>>>(x, out);   // T2 -> out  (contract i0)
}